// round 14
// baseline (speedup 1.0000x reference)
#include <cuda_runtime.h>
#include <cuda_fp16.h>
#include <stdint.h>
#include <math.h>

#define D_MODEL 1024
#define T_SEQ   2048
#define BATCH   2
#define NROWS   (BATCH * T_SEQ)
#define DFF     4096
#define NHEADS  16
#define HDIM    64

// ---------------- scratch ----------------
__device__ __align__(16) __half g_h16   [NROWS * D_MODEL];
__device__ __align__(16) __half g_qkv16 [NROWS * 3 * D_MODEL];
__device__ __align__(16) __half g_attn16[NROWS * D_MODEL];
__device__ __align__(16) float  g_x1    [NROWS * D_MODEL];
__device__ __align__(16) __half g_h2_16 [NROWS * D_MODEL];
__device__ __align__(16) __half g_ff16  [NROWS * DFF];
// fp16 weights, ORIGINAL [K][N] layout
#define SZ_QKV  (D_MODEL * 3 * D_MODEL)
#define SZ_PROJ (D_MODEL * D_MODEL)
#define SZ_MLP1 (D_MODEL * DFF)
#define SZ_MLP2 (DFF * D_MODEL)
#define W_QKV  0
#define W_PROJ (W_QKV + SZ_QKV)
#define W_MLP1 (W_PROJ + SZ_PROJ)
#define W_MLP2 (W_MLP1 + SZ_MLP1)
#define W_TOT  (W_MLP2 + SZ_MLP2)
__device__ __align__(16) __half g_w16[W_TOT];

// ---------------- helpers ----------------
__device__ __forceinline__ void mma_f16(float* d,
                                        uint32_t a0, uint32_t a1, uint32_t a2, uint32_t a3,
                                        uint32_t b0, uint32_t b1) {
    asm volatile(
        "mma.sync.aligned.m16n8k16.row.col.f32.f16.f16.f32 "
        "{%0,%1,%2,%3}, {%4,%5,%6,%7}, {%8,%9}, {%0,%1,%2,%3};\n"
        : "+f"(d[0]), "+f"(d[1]), "+f"(d[2]), "+f"(d[3])
        : "r"(a0), "r"(a1), "r"(a2), "r"(a3), "r"(b0), "r"(b1));
}

__device__ __forceinline__ void ldsm4(uint32_t& r0, uint32_t& r1, uint32_t& r2, uint32_t& r3,
                                      uint32_t addr) {
    asm volatile("ldmatrix.sync.aligned.m8n8.x4.shared.b16 {%0,%1,%2,%3}, [%4];"
                 : "=r"(r0), "=r"(r1), "=r"(r2), "=r"(r3) : "r"(addr));
}
__device__ __forceinline__ void ldsm4t(uint32_t& r0, uint32_t& r1, uint32_t& r2, uint32_t& r3,
                                       uint32_t addr) {
    asm volatile("ldmatrix.sync.aligned.m8n8.x4.trans.shared.b16 {%0,%1,%2,%3}, [%4];"
                 : "=r"(r0), "=r"(r1), "=r"(r2), "=r"(r3) : "r"(addr));
}

__device__ __forceinline__ uint32_t packh2(float lo, float hi) {
    __half2 h = __floats2half2_rn(lo, hi);
    return *reinterpret_cast<uint32_t*>(&h);
}

__device__ __forceinline__ void cp16(uint32_t s, const void* g) {
    asm volatile("cp.async.cg.shared.global [%0], [%1], 16;\n" :: "r"(s), "l"(g));
}
__device__ __forceinline__ void cp_commit() { asm volatile("cp.async.commit_group;\n"); }
__device__ __forceinline__ void cp_wait1()  { asm volatile("cp.async.wait_group 1;\n"); }

// ---------------- weight fp16 convert (streaming, [K][N] kept) ----------------
__global__ void __launch_bounds__(256)
cvt_kernel(const float* __restrict__ src, __half* __restrict__ dst, int n4) {
    const int i = blockIdx.x * blockDim.x + threadIdx.x;
    if (i < n4) {
        const float4 v = reinterpret_cast<const float4*>(src)[i];
        uint2 o;
        o.x = packh2(v.x, v.y);
        o.y = packh2(v.z, v.w);
        reinterpret_cast<uint2*>(dst)[i] = o;
    }
}

// ---------------- layernorm (fp16 output) ----------------
__global__ void ln_kernel(const float* __restrict__ x,
                          const float* __restrict__ g,
                          const float* __restrict__ b,
                          __half* __restrict__ out) {
    const int row = blockIdx.x;
    const int tid = threadIdx.x;
    const float4 v = reinterpret_cast<const float4*>(x + (size_t)row * D_MODEL)[tid];
    float s  = v.x + v.y + v.z + v.w;
    float sq = v.x*v.x + v.y*v.y + v.z*v.z + v.w*v.w;

    __shared__ float rs[256];
    __shared__ float rq[256];
    rs[tid] = s; rq[tid] = sq;
    __syncthreads();
    #pragma unroll
    for (int st = 128; st > 0; st >>= 1) {
        if (tid < st) { rs[tid] += rs[tid + st]; rq[tid] += rq[tid + st]; }
        __syncthreads();
    }
    const float mean = rs[0] * (1.0f / D_MODEL);
    const float var  = rq[0] * (1.0f / D_MODEL) - mean * mean;
    const float rstd = rsqrtf(var + 1e-5f);

    const float4 gv = reinterpret_cast<const float4*>(g)[tid];
    const float4 bv = reinterpret_cast<const float4*>(b)[tid];
    uint2 o;
    o.x = packh2((v.x - mean) * rstd * gv.x + bv.x, (v.y - mean) * rstd * gv.y + bv.y);
    o.y = packh2((v.z - mean) * rstd * gv.z + bv.z, (v.w - mean) * rstd * gv.w + bv.w);
    *reinterpret_cast<uint2*>(out + (size_t)row * D_MODEL + tid * 4) = o;
}

// ---------------- fp16 GEMM v7: 128x256 tile, 512 thr, B [K][N] trans-LDSM, 5 stages, pair ----
#define GBK   32
#define GST   40                       // A row stride halves
#define BSN   264                      // B row stride halves (256 + 8 pad)
#define A_H   (128 * GST)              // 5120 halves
#define B_H   (32 * BSN)               // 8448 halves
#define ST_H  (A_H + B_H)              // 13568 halves / stage
#define GSTAGES 5
#define GEMM_SMEM16 (GSTAGES * ST_H * 2)   // 135680 bytes

template<int EPI>
__global__ void __launch_bounds__(512, 1)
gemm16_kernel(const __half* __restrict__ A, const __half* __restrict__ B,
              const float* __restrict__ bias, const float* __restrict__ res,
              float* __restrict__ Cf, __half* __restrict__ C16,
              int M, int N, int K) {
    extern __shared__ __half smh[];
    const uint32_t smem_u32 = (uint32_t)__cvta_generic_to_shared(smh);

    const int tid    = threadIdx.x;
    const int lane   = tid & 31;
    const int warp   = tid >> 5;        // 0..15
    const int warp_m = warp >> 2;       // 0..3, 32 rows each
    const int warp_n = warp & 3;        // 0..3, 64 cols each
    const int bm = blockIdx.y * 128;
    const int bn = blockIdx.x * 256;
    const int lg = lane >> 2;
    const int lt = lane & 3;

    float c[2][8][4];
    #pragma unroll
    for (int i = 0; i < 2; i++)
        #pragma unroll
        for (int j = 0; j < 8; j++)
            #pragma unroll
            for (int k = 0; k < 4; k++) c[i][j][k] = 0.0f;

    // A: 128 rows x 64B, 4 threads/row. B: 32 rows x 512B, 16 threads/row.
    const int a_r = tid >> 2;
    const int a_c = (tid & 3) * 8;        // halves (16B)
    const int b_r = tid >> 4;
    const int b_c = (tid & 15) * 16;      // halves (32B)
    const int KT = K / GBK;

    auto load_stage = [&](int kt, int stg) {
        const uint32_t ab = smem_u32 + (stg * ST_H + a_r * GST + a_c) * 2;
        cp16(ab, &A[(size_t)(bm + a_r) * K + kt * GBK + a_c]);
        const uint32_t bb = smem_u32 + (stg * ST_H + A_H + b_r * BSN + b_c) * 2;
        const __half* bs = &B[(size_t)(kt * GBK + b_r) * N + bn + b_c];
        cp16(bb,      bs);
        cp16(bb + 16, bs + 8);
        cp_commit();
    };

    load_stage(0, 0);
    load_stage(1, 1);
    load_stage(2, 2);

    const int a_row  = warp_m * 32 + (lane & 15);             // + mi*16
    const int a_co   = (lane >> 4) * 8;
    const int bt_row = (lane & 7) + (((lane >> 3) & 1) * 8);  // k within 16-block
    const int bt_co  = (lane >> 4) * 8;                       // n sub-offset

    for (int kt = 0; kt < KT; kt += 2) {
        cp_wait1();
        __syncthreads();

        if (kt + 3 < KT) load_stage(kt + 3, (kt + 3) % GSTAGES); else cp_commit();
        if (kt + 4 < KT) load_stage(kt + 4, (kt + 4) % GSTAGES); else cp_commit();

        #pragma unroll
        for (int hf = 0; hf < 2; hf++) {
            const uint32_t abase = smem_u32 + (((kt + hf) % GSTAGES) * ST_H) * 2;
            const uint32_t bbase = abase + A_H * 2;

            #pragma unroll
            for (int ks = 0; ks < 2; ks++) {
                const int kc = ks * 16;
                uint32_t af[2][4];
                #pragma unroll
                for (int mi = 0; mi < 2; mi++)
                    ldsm4(af[mi][0], af[mi][1], af[mi][2], af[mi][3],
                          abase + (((a_row + mi * 16) * GST) + kc + a_co) * 2);
                #pragma unroll
                for (int ntp = 0; ntp < 4; ntp++) {
                    uint32_t b0, b1, b2, b3;
                    ldsm4t(b0, b1, b2, b3,
                           bbase + (((bt_row + kc) * BSN) + bt_co + warp_n * 64 + ntp * 16) * 2);
                    #pragma unroll
                    for (int mi = 0; mi < 2; mi++) {
                        mma_f16(c[mi][2 * ntp],     af[mi][0], af[mi][1], af[mi][2], af[mi][3],
                                b0, b1);
                        mma_f16(c[mi][2 * ntp + 1], af[mi][0], af[mi][1], af[mi][2], af[mi][3],
                                b2, b3);
                    }
                }
            }
        }
    }

    #pragma unroll
    for (int mi = 0; mi < 2; mi++) {
        #pragma unroll
        for (int nt = 0; nt < 8; nt++) {
            const int col = bn + warp_n * 64 + nt * 8 + 2 * lt;
            const float b0 = bias[col], b1 = bias[col + 1];
            #pragma unroll
            for (int half = 0; half < 2; half++) {
                const int row = bm + warp_m * 32 + mi * 16 + lg + half * 8;
                float v0 = c[mi][nt][half * 2 + 0] + b0;
                float v1 = c[mi][nt][half * 2 + 1] + b1;
                if (EPI == 1) {
                    v0 = 0.5f * v0 * (1.0f + erff(v0 * 0.70710678118654752f));
                    v1 = 0.5f * v1 * (1.0f + erff(v1 * 0.70710678118654752f));
                }
                if (EPI == 2) {
                    v0 += res[(size_t)row * N + col];
                    v1 += res[(size_t)row * N + col + 1];
                    float2 o; o.x = v0; o.y = v1;
                    *reinterpret_cast<float2*>(&Cf[(size_t)row * N + col]) = o;
                } else {
                    *reinterpret_cast<uint32_t*>(&C16[(size_t)row * N + col]) = packh2(v0, v1);
                }
            }
        }
    }
}

// ---------------- causal flash attention: unchanged (measured 104us) ----------------
#define QST 72
#define KST 72
#define VST 72
#define Q_SZ   (128 * QST)
#define K_OFF  Q_SZ
#define K_SZ   (64 * KST)
#define V_OFF  (K_OFF + 3 * K_SZ)
#define V_SZ   (64 * VST)
#define ATT_SMEM ((V_OFF + 3 * V_SZ) * 2)

__global__ void __launch_bounds__(256, 2)
attn_kernel(const __half* __restrict__ qkv16, __half* __restrict__ out16) {
    extern __shared__ __half smh[];
    const uint32_t smem_u32 = (uint32_t)__cvta_generic_to_shared(smh);

    const int tid  = threadIdx.x;
    const int lane = tid & 31;
    const int warp = tid >> 5;
    const int lg = lane >> 2;
    const int lt = lane & 3;

    const int qb = gridDim.x - 1 - blockIdx.x;
    const int bh = blockIdx.y;
    const int b  = bh >> 4;
    const int h  = bh & 15;
    const int q0 = qb * 128;
    const size_t rowbase = (size_t)b * T_SEQ;

    const __half* qbase = qkv16 + rowbase * (3 * D_MODEL) + h * HDIM;

    {
        const int r = tid >> 1;
        const int c = (tid & 1) * 32;
        const uint32_t qdst = smem_u32 + (r * QST + c) * 2;
        const __half* qsrc = qbase + (size_t)(q0 + r) * (3 * D_MODEL) + c;
        cp16(qdst,      qsrc);
        cp16(qdst + 16, qsrc + 8);
        cp16(qdst + 32, qsrc + 16);
        cp16(qdst + 48, qsrc + 24);
    }

    const int kv_r = tid >> 2;
    const int kv_c = (tid & 3) * 16;

    auto prefetch = [&](int kb, int stg) {
        const uint32_t kdst = smem_u32 + (K_OFF + stg * K_SZ + kv_r * KST + kv_c) * 2;
        const uint32_t vdst = smem_u32 + (V_OFF + stg * V_SZ + kv_r * VST + kv_c) * 2;
        const __half* base = qbase + (size_t)(kb * 64 + kv_r) * (3 * D_MODEL);
        cp16(kdst,      base + D_MODEL + kv_c);
        cp16(kdst + 16, base + D_MODEL + kv_c + 8);
        cp16(vdst,      base + 2 * D_MODEL + kv_c);
        cp16(vdst + 16, base + 2 * D_MODEL + kv_c + 8);
    };

    float o[8][4];
    #pragma unroll
    for (int i = 0; i < 8; i++)
        #pragma unroll
        for (int j = 0; j < 4; j++) o[i][j] = 0.0f;
    float m0 = -INFINITY, m1 = -INFINITY;
    float l0 = 0.0f, l1 = 0.0f;

    const int nkb = 2 * qb + 2;
    prefetch(0, 0); cp_commit();
    prefetch(1, 1); cp_commit();

    const int qa_row = warp * 16 + (lane & 15);
    const int qa_co  = (lane >> 4) * 8;
    const int kb_row = (lane & 7) + ((lane >> 4) * 8);
    const int kb_co  = ((lane >> 3) & 1) * 8;
    const int vt_row = (lane & 7) + (((lane >> 3) & 1) * 8);
    const int vt_co  = (lane >> 4) * 8;

    for (int kb = 0; kb < nkb; kb++) {
        cp_wait1();
        __syncthreads();

        if (kb + 2 < nkb) prefetch(kb + 2, (kb + 2) % 3);
        cp_commit();

        const int stg = kb % 3;
        const uint32_t kbase = smem_u32 + (K_OFF + stg * K_SZ) * 2;
        const uint32_t vbase = smem_u32 + (V_OFF + stg * V_SZ) * 2;

        float s[8][4];
        #pragma unroll
        for (int i = 0; i < 8; i++)
            #pragma unroll
            for (int j = 0; j < 4; j++) s[i][j] = 0.0f;
        #pragma unroll
        for (int kt = 0; kt < 4; kt++) {
            const int kc = kt * 16;
            uint32_t a0, a1, a2, a3;
            ldsm4(a0, a1, a2, a3, smem_u32 + ((qa_row * QST) + kc + qa_co) * 2);
            #pragma unroll
            for (int ntp = 0; ntp < 4; ntp++) {
                uint32_t b0, b1, b2, b3;
                ldsm4(b0, b1, b2, b3, kbase + (((kb_row + ntp * 16) * KST) + kc + kb_co) * 2);
                mma_f16(s[2 * ntp],     a0, a1, a2, a3, b0, b1);
                mma_f16(s[2 * ntp + 1], a0, a1, a2, a3, b2, b3);
            }
        }
        #pragma unroll
        for (int nt = 0; nt < 8; nt++) {
            s[nt][0] *= 0.125f; s[nt][1] *= 0.125f;
            s[nt][2] *= 0.125f; s[nt][3] *= 0.125f;
        }

        const int t0 = kb * 64;
        if (t0 + 63 > q0 + warp * 16) {
            #pragma unroll
            for (int nt = 0; nt < 8; nt++) {
                #pragma unroll
                for (int j = 0; j < 4; j++) {
                    const int trow = q0 + warp * 16 + lg + (j >= 2 ? 8 : 0);
                    const int tcol = t0 + nt * 8 + 2 * lt + (j & 1);
                    if (tcol > trow) s[nt][j] = -INFINITY;
                }
            }
        }

        float mx0 = -INFINITY, mx1 = -INFINITY;
        #pragma unroll
        for (int nt = 0; nt < 8; nt++) {
            mx0 = fmaxf(mx0, fmaxf(s[nt][0], s[nt][1]));
            mx1 = fmaxf(mx1, fmaxf(s[nt][2], s[nt][3]));
        }
        mx0 = fmaxf(mx0, __shfl_xor_sync(0xffffffff, mx0, 1));
        mx0 = fmaxf(mx0, __shfl_xor_sync(0xffffffff, mx0, 2));
        mx1 = fmaxf(mx1, __shfl_xor_sync(0xffffffff, mx1, 1));
        mx1 = fmaxf(mx1, __shfl_xor_sync(0xffffffff, mx1, 2));
        const float mn0 = fmaxf(m0, mx0);
        const float mn1 = fmaxf(m1, mx1);

        float sum0 = 0.0f, sum1 = 0.0f;
        #pragma unroll
        for (int nt = 0; nt < 8; nt++) {
            s[nt][0] = __expf(s[nt][0] - mn0);
            s[nt][1] = __expf(s[nt][1] - mn0);
            s[nt][2] = __expf(s[nt][2] - mn1);
            s[nt][3] = __expf(s[nt][3] - mn1);
            sum0 += s[nt][0] + s[nt][1];
            sum1 += s[nt][2] + s[nt][3];
        }
        sum0 += __shfl_xor_sync(0xffffffff, sum0, 1);
        sum0 += __shfl_xor_sync(0xffffffff, sum0, 2);
        sum1 += __shfl_xor_sync(0xffffffff, sum1, 1);
        sum1 += __shfl_xor_sync(0xffffffff, sum1, 2);

        const float a0f = __expf(m0 - mn0);
        const float a1f = __expf(m1 - mn1);
        l0 = l0 * a0f + sum0;
        l1 = l1 * a1f + sum1;
        m0 = mn0; m1 = mn1;
        #pragma unroll
        for (int nt = 0; nt < 8; nt++) {
            o[nt][0] *= a0f; o[nt][1] *= a0f;
            o[nt][2] *= a1f; o[nt][3] *= a1f;
        }

        #pragma unroll
        for (int kt = 0; kt < 4; kt++) {
            const uint32_t a0 = packh2(s[2*kt][0],   s[2*kt][1]);
            const uint32_t a1 = packh2(s[2*kt][2],   s[2*kt][3]);
            const uint32_t a2 = packh2(s[2*kt+1][0], s[2*kt+1][1]);
            const uint32_t a3 = packh2(s[2*kt+1][2], s[2*kt+1][3]);
            #pragma unroll
            for (int ntp = 0; ntp < 4; ntp++) {
                uint32_t b0, b1, b2, b3;
                ldsm4t(b0, b1, b2, b3,
                       vbase + (((vt_row + kt * 16) * VST) + vt_co + ntp * 16) * 2);
                mma_f16(o[2 * ntp],     a0, a1, a2, a3, b0, b1);
                mma_f16(o[2 * ntp + 1], a0, a1, a2, a3, b2, b3);
            }
        }
    }

    const float inv0 = 1.0f / l0;
    const float inv1 = 1.0f / l1;
    #pragma unroll
    for (int nt = 0; nt < 8; nt++) {
        const int dcol = h * HDIM + nt * 8 + 2 * lt;
        const size_t r0 = rowbase + q0 + warp * 16 + lg;
        *reinterpret_cast<uint32_t*>(&out16[r0 * D_MODEL + dcol]) =
            packh2(o[nt][0] * inv0, o[nt][1] * inv0);
        *reinterpret_cast<uint32_t*>(&out16[(r0 + 8) * D_MODEL + dcol]) =
            packh2(o[nt][2] * inv1, o[nt][3] * inv1);
    }
}

// ---------------- launch ----------------
extern "C" void kernel_launch(void* const* d_in, const int* in_sizes, int n_in,
                              void* d_out, int out_size) {
    const float* x      = (const float*)d_in[0];
    const float* ln1_g  = (const float*)d_in[1];
    const float* ln1_b  = (const float*)d_in[2];
    const float* qkv_w  = (const float*)d_in[3];
    const float* qkv_b  = (const float*)d_in[4];
    const float* proj_w = (const float*)d_in[5];
    const float* proj_b = (const float*)d_in[6];
    const float* ln2_g  = (const float*)d_in[7];
    const float* ln2_b  = (const float*)d_in[8];
    const float* mlp_w1 = (const float*)d_in[9];
    const float* mlp_b1 = (const float*)d_in[10];
    const float* mlp_w2 = (const float*)d_in[11];
    const float* mlp_b2 = (const float*)d_in[12];
    float* out = (float*)d_out;

    __half *h16, *qkv16, *attn16, *h2_16, *ff16, *w16;
    float *x1;
    cudaGetSymbolAddress((void**)&h16,    g_h16);
    cudaGetSymbolAddress((void**)&qkv16,  g_qkv16);
    cudaGetSymbolAddress((void**)&attn16, g_attn16);
    cudaGetSymbolAddress((void**)&x1,     g_x1);
    cudaGetSymbolAddress((void**)&h2_16,  g_h2_16);
    cudaGetSymbolAddress((void**)&ff16,   g_ff16);
    cudaGetSymbolAddress((void**)&w16,    g_w16);

    cudaFuncSetAttribute(gemm16_kernel<0>, cudaFuncAttributeMaxDynamicSharedMemorySize, GEMM_SMEM16);
    cudaFuncSetAttribute(gemm16_kernel<1>, cudaFuncAttributeMaxDynamicSharedMemorySize, GEMM_SMEM16);
    cudaFuncSetAttribute(gemm16_kernel<2>, cudaFuncAttributeMaxDynamicSharedMemorySize, GEMM_SMEM16);
    cudaFuncSetAttribute(attn_kernel,      cudaFuncAttributeMaxDynamicSharedMemorySize, ATT_SMEM);

    // 0: qkv weights -> fp16
    cvt_kernel<<<SZ_QKV / 4 / 256, 256>>>(qkv_w, w16 + W_QKV, SZ_QKV / 4);
    // 1: LN1 -> fp16
    ln_kernel<<<NROWS, 256>>>(x, ln1_g, ln1_b, h16);
    // 2: proj weights
    cvt_kernel<<<SZ_PROJ / 4 / 256, 256>>>(proj_w, w16 + W_PROJ, SZ_PROJ / 4);
    // 3: QKV GEMM -> fp16   [profiled slot]
    gemm16_kernel<0><<<dim3(3 * D_MODEL / 256, NROWS / 128), 512, GEMM_SMEM16>>>(
        h16, w16 + W_QKV, qkv_b, nullptr, nullptr, qkv16, NROWS, 3 * D_MODEL, D_MODEL);
    // 4: attention
    attn_kernel<<<dim3(T_SEQ / 128, BATCH * NHEADS), 256, ATT_SMEM>>>(qkv16, attn16);
    // 5: proj GEMM + residual (fp32)
    gemm16_kernel<2><<<dim3(D_MODEL / 256, NROWS / 128), 512, GEMM_SMEM16>>>(
        attn16, w16 + W_PROJ, proj_b, x, x1, nullptr, NROWS, D_MODEL, D_MODEL);
    // 6: LN2
    ln_kernel<<<NROWS, 256>>>(x1, ln2_g, ln2_b, h2_16);
    // 7-8: mlp1 + GELU
    cvt_kernel<<<SZ_MLP1 / 4 / 256, 256>>>(mlp_w1, w16 + W_MLP1, SZ_MLP1 / 4);
    gemm16_kernel<1><<<dim3(DFF / 256, NROWS / 128), 512, GEMM_SMEM16>>>(
        h2_16, w16 + W_MLP1, mlp_b1, nullptr, nullptr, ff16, NROWS, DFF, D_MODEL);
    // 9-10: mlp2 + residual
    cvt_kernel<<<SZ_MLP2 / 4 / 256, 256>>>(mlp_w2, w16 + W_MLP2, SZ_MLP2 / 4);
    gemm16_kernel<2><<<dim3(D_MODEL / 256, NROWS / 128), 512, GEMM_SMEM16>>>(
        ff16, w16 + W_MLP2, mlp_b2, x1, out, nullptr, NROWS, D_MODEL, DFF);
}

// round 15
// speedup vs baseline: 1.0305x; 1.0305x over previous
#include <cuda_runtime.h>
#include <cuda_fp16.h>
#include <stdint.h>
#include <math.h>

#define D_MODEL 1024
#define T_SEQ   2048
#define BATCH   2
#define NROWS   (BATCH * T_SEQ)
#define DFF     4096
#define NHEADS  16
#define HDIM    64

// ---------------- scratch ----------------
__device__ __align__(16) __half g_h16   [NROWS * D_MODEL];
__device__ __align__(16) __half g_qkv16 [NROWS * 3 * D_MODEL];
__device__ __align__(16) __half g_attn16[NROWS * D_MODEL];
__device__ __align__(16) float  g_x1    [NROWS * D_MODEL];
__device__ __align__(16) __half g_h2_16 [NROWS * D_MODEL];
__device__ __align__(16) __half g_ff16  [NROWS * DFF];
// fp16 weights, ORIGINAL [K][N] layout
#define SZ_QKV  (D_MODEL * 3 * D_MODEL)
#define SZ_PROJ (D_MODEL * D_MODEL)
#define SZ_MLP1 (D_MODEL * DFF)
#define SZ_MLP2 (DFF * D_MODEL)
#define W_QKV  0
#define W_PROJ (W_QKV + SZ_QKV)
#define W_MLP1 (W_PROJ + SZ_PROJ)
#define W_MLP2 (W_MLP1 + SZ_MLP1)
#define W_TOT  (W_MLP2 + SZ_MLP2)
__device__ __align__(16) __half g_w16[W_TOT];

// ---------------- helpers ----------------
__device__ __forceinline__ void mma_f16(float* d,
                                        uint32_t a0, uint32_t a1, uint32_t a2, uint32_t a3,
                                        uint32_t b0, uint32_t b1) {
    asm volatile(
        "mma.sync.aligned.m16n8k16.row.col.f32.f16.f16.f32 "
        "{%0,%1,%2,%3}, {%4,%5,%6,%7}, {%8,%9}, {%0,%1,%2,%3};\n"
        : "+f"(d[0]), "+f"(d[1]), "+f"(d[2]), "+f"(d[3])
        : "r"(a0), "r"(a1), "r"(a2), "r"(a3), "r"(b0), "r"(b1));
}

__device__ __forceinline__ void ldsm4(uint32_t& r0, uint32_t& r1, uint32_t& r2, uint32_t& r3,
                                      uint32_t addr) {
    asm volatile("ldmatrix.sync.aligned.m8n8.x4.shared.b16 {%0,%1,%2,%3}, [%4];"
                 : "=r"(r0), "=r"(r1), "=r"(r2), "=r"(r3) : "r"(addr));
}
__device__ __forceinline__ void ldsm4t(uint32_t& r0, uint32_t& r1, uint32_t& r2, uint32_t& r3,
                                       uint32_t addr) {
    asm volatile("ldmatrix.sync.aligned.m8n8.x4.trans.shared.b16 {%0,%1,%2,%3}, [%4];"
                 : "=r"(r0), "=r"(r1), "=r"(r2), "=r"(r3) : "r"(addr));
}

__device__ __forceinline__ uint32_t packh2(float lo, float hi) {
    __half2 h = __floats2half2_rn(lo, hi);
    return *reinterpret_cast<uint32_t*>(&h);
}

__device__ __forceinline__ void cp16(uint32_t s, const void* g) {
    asm volatile("cp.async.cg.shared.global [%0], [%1], 16;\n" :: "r"(s), "l"(g));
}
__device__ __forceinline__ void cp_commit() { asm volatile("cp.async.commit_group;\n"); }
__device__ __forceinline__ void cp_wait1()  { asm volatile("cp.async.wait_group 1;\n"); }

// ---------------- merged weight fp16 convert (one launch, 4 sources) ----------------
__global__ void __launch_bounds__(256)
cvt_all_kernel(const float* __restrict__ s0, const float* __restrict__ s1,
               const float* __restrict__ s2, const float* __restrict__ s3,
               __half* __restrict__ dst) {
    const int i = blockIdx.x * blockDim.x + threadIdx.x;   // float4 index
    const int e = i * 4;                                    // element index
    const float* src;
    int off;
    if (e < W_PROJ)      { src = s0; off = e - W_QKV;  }
    else if (e < W_MLP1) { src = s1; off = e - W_PROJ; }
    else if (e < W_MLP2) { src = s2; off = e - W_MLP1; }
    else                 { src = s3; off = e - W_MLP2; }
    const float4 v = *reinterpret_cast<const float4*>(src + off);
    uint2 o;
    o.x = packh2(v.x, v.y);
    o.y = packh2(v.z, v.w);
    reinterpret_cast<uint2*>(dst)[i] = o;
}

// ---------------- layernorm (fp16 output) ----------------
__global__ void ln_kernel(const float* __restrict__ x,
                          const float* __restrict__ g,
                          const float* __restrict__ b,
                          __half* __restrict__ out) {
    const int row = blockIdx.x;
    const int tid = threadIdx.x;
    const float4 v = reinterpret_cast<const float4*>(x + (size_t)row * D_MODEL)[tid];
    float s  = v.x + v.y + v.z + v.w;
    float sq = v.x*v.x + v.y*v.y + v.z*v.z + v.w*v.w;

    __shared__ float rs[256];
    __shared__ float rq[256];
    rs[tid] = s; rq[tid] = sq;
    __syncthreads();
    #pragma unroll
    for (int st = 128; st > 0; st >>= 1) {
        if (tid < st) { rs[tid] += rs[tid + st]; rq[tid] += rq[tid + st]; }
        __syncthreads();
    }
    const float mean = rs[0] * (1.0f / D_MODEL);
    const float var  = rq[0] * (1.0f / D_MODEL) - mean * mean;
    const float rstd = rsqrtf(var + 1e-5f);

    const float4 gv = reinterpret_cast<const float4*>(g)[tid];
    const float4 bv = reinterpret_cast<const float4*>(b)[tid];
    uint2 o;
    o.x = packh2((v.x - mean) * rstd * gv.x + bv.x, (v.y - mean) * rstd * gv.y + bv.y);
    o.y = packh2((v.z - mean) * rstd * gv.z + bv.z, (v.w - mean) * rstd * gv.w + bv.w);
    *reinterpret_cast<uint2*>(out + (size_t)row * D_MODEL + tid * 4) = o;
}

// ---------------- fp16 GEMM (R13 proven): 128x128, B [K][N] trans-LDSM, 5 stages, pair ----
#define GBK   32
#define GST   40
#define BSN   136
#define A_H   (128 * GST)
#define B_H   (32 * BSN)
#define ST_H  (A_H + B_H)
#define GSTAGES 5
#define GEMM_SMEM16 (GSTAGES * ST_H * 2)   // 94720 bytes

template<int EPI>
__global__ void __launch_bounds__(256, 2)
gemm16_kernel(const __half* __restrict__ A, const __half* __restrict__ B,
              const float* __restrict__ bias, const float* __restrict__ res,
              float* __restrict__ Cf, __half* __restrict__ C16,
              int M, int N, int K) {
    extern __shared__ __half smh[];
    const uint32_t smem_u32 = (uint32_t)__cvta_generic_to_shared(smh);

    const int tid    = threadIdx.x;
    const int lane   = tid & 31;
    const int warp   = tid >> 5;
    const int warp_m = warp >> 1;
    const int warp_n = warp & 1;
    const int bm = blockIdx.y * 128;
    const int bn = blockIdx.x * 128;
    const int lg = lane >> 2;
    const int lt = lane & 3;

    float c[2][8][4];
    #pragma unroll
    for (int i = 0; i < 2; i++)
        #pragma unroll
        for (int j = 0; j < 8; j++)
            #pragma unroll
            for (int k = 0; k < 4; k++) c[i][j][k] = 0.0f;

    const int a_r = tid >> 1;
    const int a_c = (tid & 1) * 16;
    const int b_r = tid >> 3;
    const int b_c = (tid & 7) * 16;
    const int KT = K / GBK;

    auto load_stage = [&](int kt, int stg) {
        const uint32_t ab = smem_u32 + (stg * ST_H + a_r * GST + a_c) * 2;
        const __half* as = &A[(size_t)(bm + a_r) * K + kt * GBK + a_c];
        cp16(ab,      as);
        cp16(ab + 16, as + 8);
        const uint32_t bb = smem_u32 + (stg * ST_H + A_H + b_r * BSN + b_c) * 2;
        const __half* bs = &B[(size_t)(kt * GBK + b_r) * N + bn + b_c];
        cp16(bb,      bs);
        cp16(bb + 16, bs + 8);
        cp_commit();
    };

    load_stage(0, 0);
    load_stage(1, 1);
    load_stage(2, 2);

    const int a_row  = warp_m * 32 + (lane & 15);
    const int a_co   = (lane >> 4) * 8;
    const int bt_row = (lane & 7) + (((lane >> 3) & 1) * 8);
    const int bt_co  = (lane >> 4) * 8;

    for (int kt = 0; kt < KT; kt += 2) {
        cp_wait1();
        __syncthreads();

        if (kt + 3 < KT) load_stage(kt + 3, (kt + 3) % GSTAGES); else cp_commit();
        if (kt + 4 < KT) load_stage(kt + 4, (kt + 4) % GSTAGES); else cp_commit();

        #pragma unroll
        for (int hf = 0; hf < 2; hf++) {
            const uint32_t abase = smem_u32 + (((kt + hf) % GSTAGES) * ST_H) * 2;
            const uint32_t bbase = abase + A_H * 2;

            #pragma unroll
            for (int ks = 0; ks < 2; ks++) {
                const int kc = ks * 16;
                uint32_t af[2][4];
                #pragma unroll
                for (int mi = 0; mi < 2; mi++)
                    ldsm4(af[mi][0], af[mi][1], af[mi][2], af[mi][3],
                          abase + (((a_row + mi * 16) * GST) + kc + a_co) * 2);
                #pragma unroll
                for (int ntp = 0; ntp < 4; ntp++) {
                    uint32_t b0, b1, b2, b3;
                    ldsm4t(b0, b1, b2, b3,
                           bbase + (((bt_row + kc) * BSN) + bt_co + warp_n * 64 + ntp * 16) * 2);
                    #pragma unroll
                    for (int mi = 0; mi < 2; mi++) {
                        mma_f16(c[mi][2 * ntp],     af[mi][0], af[mi][1], af[mi][2], af[mi][3],
                                b0, b1);
                        mma_f16(c[mi][2 * ntp + 1], af[mi][0], af[mi][1], af[mi][2], af[mi][3],
                                b2, b3);
                    }
                }
            }
        }
    }

    #pragma unroll
    for (int mi = 0; mi < 2; mi++) {
        #pragma unroll
        for (int nt = 0; nt < 8; nt++) {
            const int col = bn + warp_n * 64 + nt * 8 + 2 * lt;
            const float b0 = bias[col], b1 = bias[col + 1];
            #pragma unroll
            for (int half = 0; half < 2; half++) {
                const int row = bm + warp_m * 32 + mi * 16 + lg + half * 8;
                float v0 = c[mi][nt][half * 2 + 0] + b0;
                float v1 = c[mi][nt][half * 2 + 1] + b1;
                if (EPI == 1) {
                    v0 = 0.5f * v0 * (1.0f + erff(v0 * 0.70710678118654752f));
                    v1 = 0.5f * v1 * (1.0f + erff(v1 * 0.70710678118654752f));
                }
                if (EPI == 2) {
                    v0 += res[(size_t)row * N + col];
                    v1 += res[(size_t)row * N + col + 1];
                    float2 o; o.x = v0; o.y = v1;
                    *reinterpret_cast<float2*>(&Cf[(size_t)row * N + col]) = o;
                } else {
                    *reinterpret_cast<uint32_t*>(&C16[(size_t)row * N + col]) = packh2(v0, v1);
                }
            }
        }
    }
}

// ---------------- causal flash attention (exp2-domain softmax) ----------------
#define QST 72
#define KST 72
#define VST 72
#define Q_SZ   (128 * QST)
#define K_OFF  Q_SZ
#define K_SZ   (64 * KST)
#define V_OFF  (K_OFF + 3 * K_SZ)
#define V_SZ   (64 * VST)
#define ATT_SMEM ((V_OFF + 3 * V_SZ) * 2)
#define S_SCALE (0.125f * 1.4426950408889634f)   // (1/8) * log2(e)

__global__ void __launch_bounds__(256, 2)
attn_kernel(const __half* __restrict__ qkv16, __half* __restrict__ out16) {
    extern __shared__ __half smh[];
    const uint32_t smem_u32 = (uint32_t)__cvta_generic_to_shared(smh);

    const int tid  = threadIdx.x;
    const int lane = tid & 31;
    const int warp = tid >> 5;
    const int lg = lane >> 2;
    const int lt = lane & 3;

    const int qb = gridDim.x - 1 - blockIdx.x;
    const int bh = blockIdx.y;
    const int b  = bh >> 4;
    const int h  = bh & 15;
    const int q0 = qb * 128;
    const size_t rowbase = (size_t)b * T_SEQ;

    const __half* qbase = qkv16 + rowbase * (3 * D_MODEL) + h * HDIM;

    {
        const int r = tid >> 1;
        const int c = (tid & 1) * 32;
        const uint32_t qdst = smem_u32 + (r * QST + c) * 2;
        const __half* qsrc = qbase + (size_t)(q0 + r) * (3 * D_MODEL) + c;
        cp16(qdst,      qsrc);
        cp16(qdst + 16, qsrc + 8);
        cp16(qdst + 32, qsrc + 16);
        cp16(qdst + 48, qsrc + 24);
    }

    const int kv_r = tid >> 2;
    const int kv_c = (tid & 3) * 16;

    auto prefetch = [&](int kb, int stg) {
        const uint32_t kdst = smem_u32 + (K_OFF + stg * K_SZ + kv_r * KST + kv_c) * 2;
        const uint32_t vdst = smem_u32 + (V_OFF + stg * V_SZ + kv_r * VST + kv_c) * 2;
        const __half* base = qbase + (size_t)(kb * 64 + kv_r) * (3 * D_MODEL);
        cp16(kdst,      base + D_MODEL + kv_c);
        cp16(kdst + 16, base + D_MODEL + kv_c + 8);
        cp16(vdst,      base + 2 * D_MODEL + kv_c);
        cp16(vdst + 16, base + 2 * D_MODEL + kv_c + 8);
    };

    float o[8][4];
    #pragma unroll
    for (int i = 0; i < 8; i++)
        #pragma unroll
        for (int j = 0; j < 4; j++) o[i][j] = 0.0f;
    float m0 = -INFINITY, m1 = -INFINITY;
    float l0 = 0.0f, l1 = 0.0f;

    const int nkb = 2 * qb + 2;
    prefetch(0, 0); cp_commit();
    prefetch(1, 1); cp_commit();

    const int qa_row = warp * 16 + (lane & 15);
    const int qa_co  = (lane >> 4) * 8;
    const int kb_row = (lane & 7) + ((lane >> 4) * 8);
    const int kb_co  = ((lane >> 3) & 1) * 8;
    const int vt_row = (lane & 7) + (((lane >> 3) & 1) * 8);
    const int vt_co  = (lane >> 4) * 8;

    for (int kb = 0; kb < nkb; kb++) {
        cp_wait1();
        __syncthreads();

        if (kb + 2 < nkb) prefetch(kb + 2, (kb + 2) % 3);
        cp_commit();

        const int stg = kb % 3;
        const uint32_t kbase = smem_u32 + (K_OFF + stg * K_SZ) * 2;
        const uint32_t vbase = smem_u32 + (V_OFF + stg * V_SZ) * 2;

        float s[8][4];
        #pragma unroll
        for (int i = 0; i < 8; i++)
            #pragma unroll
            for (int j = 0; j < 4; j++) s[i][j] = 0.0f;
        #pragma unroll
        for (int kt = 0; kt < 4; kt++) {
            const int kc = kt * 16;
            uint32_t a0, a1, a2, a3;
            ldsm4(a0, a1, a2, a3, smem_u32 + ((qa_row * QST) + kc + qa_co) * 2);
            #pragma unroll
            for (int ntp = 0; ntp < 4; ntp++) {
                uint32_t b0, b1, b2, b3;
                ldsm4(b0, b1, b2, b3, kbase + (((kb_row + ntp * 16) * KST) + kc + kb_co) * 2);
                mma_f16(s[2 * ntp],     a0, a1, a2, a3, b0, b1);
                mma_f16(s[2 * ntp + 1], a0, a1, a2, a3, b2, b3);
            }
        }
        // scale into exp2 domain: s = (QK/8)·log2e
        #pragma unroll
        for (int nt = 0; nt < 8; nt++) {
            s[nt][0] *= S_SCALE; s[nt][1] *= S_SCALE;
            s[nt][2] *= S_SCALE; s[nt][3] *= S_SCALE;
        }

        const int t0 = kb * 64;
        if (t0 + 63 > q0 + warp * 16) {
            #pragma unroll
            for (int nt = 0; nt < 8; nt++) {
                #pragma unroll
                for (int j = 0; j < 4; j++) {
                    const int trow = q0 + warp * 16 + lg + (j >= 2 ? 8 : 0);
                    const int tcol = t0 + nt * 8 + 2 * lt + (j & 1);
                    if (tcol > trow) s[nt][j] = -INFINITY;
                }
            }
        }

        float mx0 = -INFINITY, mx1 = -INFINITY;
        #pragma unroll
        for (int nt = 0; nt < 8; nt++) {
            mx0 = fmaxf(mx0, fmaxf(s[nt][0], s[nt][1]));
            mx1 = fmaxf(mx1, fmaxf(s[nt][2], s[nt][3]));
        }
        mx0 = fmaxf(mx0, __shfl_xor_sync(0xffffffff, mx0, 1));
        mx0 = fmaxf(mx0, __shfl_xor_sync(0xffffffff, mx0, 2));
        mx1 = fmaxf(mx1, __shfl_xor_sync(0xffffffff, mx1, 1));
        mx1 = fmaxf(mx1, __shfl_xor_sync(0xffffffff, mx1, 2));
        const float mn0 = fmaxf(m0, mx0);
        const float mn1 = fmaxf(m1, mx1);

        float sum0 = 0.0f, sum1 = 0.0f;
        #pragma unroll
        for (int nt = 0; nt < 8; nt++) {
            s[nt][0] = exp2f(s[nt][0] - mn0);
            s[nt][1] = exp2f(s[nt][1] - mn0);
            s[nt][2] = exp2f(s[nt][2] - mn1);
            s[nt][3] = exp2f(s[nt][3] - mn1);
            sum0 += s[nt][0] + s[nt][1];
            sum1 += s[nt][2] + s[nt][3];
        }
        sum0 += __shfl_xor_sync(0xffffffff, sum0, 1);
        sum0 += __shfl_xor_sync(0xffffffff, sum0, 2);
        sum1 += __shfl_xor_sync(0xffffffff, sum1, 1);
        sum1 += __shfl_xor_sync(0xffffffff, sum1, 2);

        const float a0f = exp2f(m0 - mn0);
        const float a1f = exp2f(m1 - mn1);
        l0 = l0 * a0f + sum0;
        l1 = l1 * a1f + sum1;
        m0 = mn0; m1 = mn1;
        #pragma unroll
        for (int nt = 0; nt < 8; nt++) {
            o[nt][0] *= a0f; o[nt][1] *= a0f;
            o[nt][2] *= a1f; o[nt][3] *= a1f;
        }

        #pragma unroll
        for (int kt = 0; kt < 4; kt++) {
            const uint32_t a0 = packh2(s[2*kt][0],   s[2*kt][1]);
            const uint32_t a1 = packh2(s[2*kt][2],   s[2*kt][3]);
            const uint32_t a2 = packh2(s[2*kt+1][0], s[2*kt+1][1]);
            const uint32_t a3 = packh2(s[2*kt+1][2], s[2*kt+1][3]);
            #pragma unroll
            for (int ntp = 0; ntp < 4; ntp++) {
                uint32_t b0, b1, b2, b3;
                ldsm4t(b0, b1, b2, b3,
                       vbase + (((vt_row + kt * 16) * VST) + vt_co + ntp * 16) * 2);
                mma_f16(o[2 * ntp],     a0, a1, a2, a3, b0, b1);
                mma_f16(o[2 * ntp + 1], a0, a1, a2, a3, b2, b3);
            }
        }
    }

    const float inv0 = 1.0f / l0;
    const float inv1 = 1.0f / l1;
    #pragma unroll
    for (int nt = 0; nt < 8; nt++) {
        const int dcol = h * HDIM + nt * 8 + 2 * lt;
        const size_t r0 = rowbase + q0 + warp * 16 + lg;
        *reinterpret_cast<uint32_t*>(&out16[r0 * D_MODEL + dcol]) =
            packh2(o[nt][0] * inv0, o[nt][1] * inv0);
        *reinterpret_cast<uint32_t*>(&out16[(r0 + 8) * D_MODEL + dcol]) =
            packh2(o[nt][2] * inv1, o[nt][3] * inv1);
    }
}

// ---------------- launch ----------------
extern "C" void kernel_launch(void* const* d_in, const int* in_sizes, int n_in,
                              void* d_out, int out_size) {
    const float* x      = (const float*)d_in[0];
    const float* ln1_g  = (const float*)d_in[1];
    const float* ln1_b  = (const float*)d_in[2];
    const float* qkv_w  = (const float*)d_in[3];
    const float* qkv_b  = (const float*)d_in[4];
    const float* proj_w = (const float*)d_in[5];
    const float* proj_b = (const float*)d_in[6];
    const float* ln2_g  = (const float*)d_in[7];
    const float* ln2_b  = (const float*)d_in[8];
    const float* mlp_w1 = (const float*)d_in[9];
    const float* mlp_b1 = (const float*)d_in[10];
    const float* mlp_w2 = (const float*)d_in[11];
    const float* mlp_b2 = (const float*)d_in[12];
    float* out = (float*)d_out;

    __half *h16, *qkv16, *attn16, *h2_16, *ff16, *w16;
    float *x1;
    cudaGetSymbolAddress((void**)&h16,    g_h16);
    cudaGetSymbolAddress((void**)&qkv16,  g_qkv16);
    cudaGetSymbolAddress((void**)&attn16, g_attn16);
    cudaGetSymbolAddress((void**)&x1,     g_x1);
    cudaGetSymbolAddress((void**)&h2_16,  g_h2_16);
    cudaGetSymbolAddress((void**)&ff16,   g_ff16);
    cudaGetSymbolAddress((void**)&w16,    g_w16);

    cudaFuncSetAttribute(gemm16_kernel<0>, cudaFuncAttributeMaxDynamicSharedMemorySize, GEMM_SMEM16);
    cudaFuncSetAttribute(gemm16_kernel<1>, cudaFuncAttributeMaxDynamicSharedMemorySize, GEMM_SMEM16);
    cudaFuncSetAttribute(gemm16_kernel<2>, cudaFuncAttributeMaxDynamicSharedMemorySize, GEMM_SMEM16);
    cudaFuncSetAttribute(attn_kernel,      cudaFuncAttributeMaxDynamicSharedMemorySize, ATT_SMEM);

    // 0: ALL weights -> fp16, single launch
    cvt_all_kernel<<<W_TOT / 4 / 256, 256>>>(qkv_w, proj_w, mlp_w1, mlp_w2, w16);
    // 1: LN1 -> fp16
    ln_kernel<<<NROWS, 256>>>(x, ln1_g, ln1_b, h16);
    // 2: QKV GEMM -> fp16
    gemm16_kernel<0><<<dim3(3 * D_MODEL / 128, NROWS / 128), 256, GEMM_SMEM16>>>(
        h16, w16 + W_QKV, qkv_b, nullptr, nullptr, qkv16, NROWS, 3 * D_MODEL, D_MODEL);
    // 3: attention
    attn_kernel<<<dim3(T_SEQ / 128, BATCH * NHEADS), 256, ATT_SMEM>>>(qkv16, attn16);
    // 4: proj GEMM + residual (fp32)
    gemm16_kernel<2><<<dim3(D_MODEL / 128, NROWS / 128), 256, GEMM_SMEM16>>>(
        attn16, w16 + W_PROJ, proj_b, x, x1, nullptr, NROWS, D_MODEL, D_MODEL);
    // 5: LN2
    ln_kernel<<<NROWS, 256>>>(x1, ln2_g, ln2_b, h2_16);
    // 6: mlp1 + GELU
    gemm16_kernel<1><<<dim3(DFF / 128, NROWS / 128), 256, GEMM_SMEM16>>>(
        h2_16, w16 + W_MLP1, mlp_b1, nullptr, nullptr, ff16, NROWS, DFF, D_MODEL);
    // 7: mlp2 + residual
    gemm16_kernel<2><<<dim3(D_MODEL / 128, NROWS / 128), 256, GEMM_SMEM16>>>(
        ff16, w16 + W_MLP2, mlp_b2, x1, out, nullptr, NROWS, D_MODEL, DFF);
}

// round 16
// speedup vs baseline: 1.0336x; 1.0030x over previous
#include <cuda_runtime.h>
#include <cuda_fp16.h>
#include <stdint.h>
#include <math.h>

#define D_MODEL 1024
#define T_SEQ   2048
#define BATCH   2
#define NROWS   (BATCH * T_SEQ)
#define DFF     4096
#define NHEADS  16
#define HDIM    64

// ---------------- scratch ----------------
__device__ __align__(16) __half g_h16   [NROWS * D_MODEL];
__device__ __align__(16) __half g_qkv16 [NROWS * 3 * D_MODEL];
__device__ __align__(16) __half g_attn16[NROWS * D_MODEL];
__device__ __align__(16) float  g_x1    [NROWS * D_MODEL];
__device__ __align__(16) __half g_h2_16 [NROWS * D_MODEL];
__device__ __align__(16) __half g_ff16  [NROWS * DFF];
// fp16 weights, ORIGINAL [K][N] layout
#define SZ_QKV  (D_MODEL * 3 * D_MODEL)
#define SZ_PROJ (D_MODEL * D_MODEL)
#define SZ_MLP1 (D_MODEL * DFF)
#define SZ_MLP2 (DFF * D_MODEL)
#define W_QKV  0
#define W_PROJ (W_QKV + SZ_QKV)
#define W_MLP1 (W_PROJ + SZ_PROJ)
#define W_MLP2 (W_MLP1 + SZ_MLP1)
#define W_TOT  (W_MLP2 + SZ_MLP2)
__device__ __align__(16) __half g_w16[W_TOT];

// ---------------- helpers ----------------
__device__ __forceinline__ void mma_f16(float* d,
                                        uint32_t a0, uint32_t a1, uint32_t a2, uint32_t a3,
                                        uint32_t b0, uint32_t b1) {
    asm volatile(
        "mma.sync.aligned.m16n8k16.row.col.f32.f16.f16.f32 "
        "{%0,%1,%2,%3}, {%4,%5,%6,%7}, {%8,%9}, {%0,%1,%2,%3};\n"
        : "+f"(d[0]), "+f"(d[1]), "+f"(d[2]), "+f"(d[3])
        : "r"(a0), "r"(a1), "r"(a2), "r"(a3), "r"(b0), "r"(b1));
}

__device__ __forceinline__ void ldsm4(uint32_t& r0, uint32_t& r1, uint32_t& r2, uint32_t& r3,
                                      uint32_t addr) {
    asm volatile("ldmatrix.sync.aligned.m8n8.x4.shared.b16 {%0,%1,%2,%3}, [%4];"
                 : "=r"(r0), "=r"(r1), "=r"(r2), "=r"(r3) : "r"(addr));
}
__device__ __forceinline__ void ldsm4t(uint32_t& r0, uint32_t& r1, uint32_t& r2, uint32_t& r3,
                                       uint32_t addr) {
    asm volatile("ldmatrix.sync.aligned.m8n8.x4.trans.shared.b16 {%0,%1,%2,%3}, [%4];"
                 : "=r"(r0), "=r"(r1), "=r"(r2), "=r"(r3) : "r"(addr));
}

__device__ __forceinline__ uint32_t packh2(float lo, float hi) {
    __half2 h = __floats2half2_rn(lo, hi);
    return *reinterpret_cast<uint32_t*>(&h);
}

__device__ __forceinline__ void cp16(uint32_t s, const void* g) {
    asm volatile("cp.async.cg.shared.global [%0], [%1], 16;\n" :: "r"(s), "l"(g));
}
__device__ __forceinline__ void cp_commit() { asm volatile("cp.async.commit_group;\n"); }
__device__ __forceinline__ void cp_wait1()  { asm volatile("cp.async.wait_group 1;\n"); }

// ---------------- merged weight fp16 convert (one launch, 4 sources) ----------------
__global__ void __launch_bounds__(256)
cvt_all_kernel(const float* __restrict__ s0, const float* __restrict__ s1,
               const float* __restrict__ s2, const float* __restrict__ s3,
               __half* __restrict__ dst) {
    const int i = blockIdx.x * blockDim.x + threadIdx.x;   // float4 index
    const int e = i * 4;                                    // element index
    const float* src;
    int off;
    if (e < W_PROJ)      { src = s0; off = e - W_QKV;  }
    else if (e < W_MLP1) { src = s1; off = e - W_PROJ; }
    else if (e < W_MLP2) { src = s2; off = e - W_MLP1; }
    else                 { src = s3; off = e - W_MLP2; }
    const float4 v = *reinterpret_cast<const float4*>(src + off);
    uint2 o;
    o.x = packh2(v.x, v.y);
    o.y = packh2(v.z, v.w);
    reinterpret_cast<uint2*>(dst)[i] = o;
}

// ---------------- layernorm (fp16 output) ----------------
__global__ void ln_kernel(const float* __restrict__ x,
                          const float* __restrict__ g,
                          const float* __restrict__ b,
                          __half* __restrict__ out) {
    const int row = blockIdx.x;
    const int tid = threadIdx.x;
    const float4 v = reinterpret_cast<const float4*>(x + (size_t)row * D_MODEL)[tid];
    float s  = v.x + v.y + v.z + v.w;
    float sq = v.x*v.x + v.y*v.y + v.z*v.z + v.w*v.w;

    __shared__ float rs[256];
    __shared__ float rq[256];
    rs[tid] = s; rq[tid] = sq;
    __syncthreads();
    #pragma unroll
    for (int st = 128; st > 0; st >>= 1) {
        if (tid < st) { rs[tid] += rs[tid + st]; rq[tid] += rq[tid + st]; }
        __syncthreads();
    }
    const float mean = rs[0] * (1.0f / D_MODEL);
    const float var  = rq[0] * (1.0f / D_MODEL) - mean * mean;
    const float rstd = rsqrtf(var + 1e-5f);

    const float4 gv = reinterpret_cast<const float4*>(g)[tid];
    const float4 bv = reinterpret_cast<const float4*>(b)[tid];
    uint2 o;
    o.x = packh2((v.x - mean) * rstd * gv.x + bv.x, (v.y - mean) * rstd * gv.y + bv.y);
    o.y = packh2((v.z - mean) * rstd * gv.z + bv.z, (v.w - mean) * rstd * gv.w + bv.w);
    *reinterpret_cast<uint2*>(out + (size_t)row * D_MODEL + tid * 4) = o;
}

// ---------------- fp16 GEMM (proven): 128x128, B [K][N] trans-LDSM, 5 stages, pair ----
#define GBK   32
#define GST   40
#define BSN   136
#define A_H   (128 * GST)
#define B_H   (32 * BSN)
#define ST_H  (A_H + B_H)
#define GSTAGES 5
#define GEMM_SMEM16 (GSTAGES * ST_H * 2)   // 94720 bytes

template<int EPI>
__global__ void __launch_bounds__(256, 2)
gemm16_kernel(const __half* __restrict__ A, const __half* __restrict__ B,
              const float* __restrict__ bias, const float* __restrict__ res,
              float* __restrict__ Cf, __half* __restrict__ C16,
              int M, int N, int K) {
    extern __shared__ __half smh[];
    const uint32_t smem_u32 = (uint32_t)__cvta_generic_to_shared(smh);

    const int tid    = threadIdx.x;
    const int lane   = tid & 31;
    const int warp   = tid >> 5;
    const int warp_m = warp >> 1;
    const int warp_n = warp & 1;
    const int bm = blockIdx.y * 128;
    const int bn = blockIdx.x * 128;
    const int lg = lane >> 2;
    const int lt = lane & 3;

    float c[2][8][4];
    #pragma unroll
    for (int i = 0; i < 2; i++)
        #pragma unroll
        for (int j = 0; j < 8; j++)
            #pragma unroll
            for (int k = 0; k < 4; k++) c[i][j][k] = 0.0f;

    const int a_r = tid >> 1;
    const int a_c = (tid & 1) * 16;
    const int b_r = tid >> 3;
    const int b_c = (tid & 7) * 16;
    const int KT = K / GBK;

    auto load_stage = [&](int kt, int stg) {
        const uint32_t ab = smem_u32 + (stg * ST_H + a_r * GST + a_c) * 2;
        const __half* as = &A[(size_t)(bm + a_r) * K + kt * GBK + a_c];
        cp16(ab,      as);
        cp16(ab + 16, as + 8);
        const uint32_t bb = smem_u32 + (stg * ST_H + A_H + b_r * BSN + b_c) * 2;
        const __half* bs = &B[(size_t)(kt * GBK + b_r) * N + bn + b_c];
        cp16(bb,      bs);
        cp16(bb + 16, bs + 8);
        cp_commit();
    };

    load_stage(0, 0);
    load_stage(1, 1);
    load_stage(2, 2);

    const int a_row  = warp_m * 32 + (lane & 15);
    const int a_co   = (lane >> 4) * 8;
    const int bt_row = (lane & 7) + (((lane >> 3) & 1) * 8);
    const int bt_co  = (lane >> 4) * 8;

    for (int kt = 0; kt < KT; kt += 2) {
        cp_wait1();
        __syncthreads();

        if (kt + 3 < KT) load_stage(kt + 3, (kt + 3) % GSTAGES); else cp_commit();
        if (kt + 4 < KT) load_stage(kt + 4, (kt + 4) % GSTAGES); else cp_commit();

        #pragma unroll
        for (int hf = 0; hf < 2; hf++) {
            const uint32_t abase = smem_u32 + (((kt + hf) % GSTAGES) * ST_H) * 2;
            const uint32_t bbase = abase + A_H * 2;

            #pragma unroll
            for (int ks = 0; ks < 2; ks++) {
                const int kc = ks * 16;
                uint32_t af[2][4];
                #pragma unroll
                for (int mi = 0; mi < 2; mi++)
                    ldsm4(af[mi][0], af[mi][1], af[mi][2], af[mi][3],
                          abase + (((a_row + mi * 16) * GST) + kc + a_co) * 2);
                #pragma unroll
                for (int ntp = 0; ntp < 4; ntp++) {
                    uint32_t b0, b1, b2, b3;
                    ldsm4t(b0, b1, b2, b3,
                           bbase + (((bt_row + kc) * BSN) + bt_co + warp_n * 64 + ntp * 16) * 2);
                    #pragma unroll
                    for (int mi = 0; mi < 2; mi++) {
                        mma_f16(c[mi][2 * ntp],     af[mi][0], af[mi][1], af[mi][2], af[mi][3],
                                b0, b1);
                        mma_f16(c[mi][2 * ntp + 1], af[mi][0], af[mi][1], af[mi][2], af[mi][3],
                                b2, b3);
                    }
                }
            }
        }
    }

    const float inv_sqrt2 = 0.70710678118654752f;
    #pragma unroll
    for (int mi = 0; mi < 2; mi++) {
        #pragma unroll
        for (int nt = 0; nt < 8; nt++) {
            const int col = bn + warp_n * 64 + nt * 8 + 2 * lt;
            const float2 bb = *reinterpret_cast<const float2*>(&bias[col]);
            #pragma unroll
            for (int half = 0; half < 2; half++) {
                const int row = bm + warp_m * 32 + mi * 16 + lg + half * 8;
                float v0 = c[mi][nt][half * 2 + 0] + bb.x;
                float v1 = c[mi][nt][half * 2 + 1] + bb.y;
                if (EPI == 1) {
                    v0 = 0.5f * v0 * (1.0f + erff(v0 * inv_sqrt2));
                    v1 = 0.5f * v1 * (1.0f + erff(v1 * inv_sqrt2));
                }
                if (EPI == 2) {
                    const float2 rv = *reinterpret_cast<const float2*>(&res[(size_t)row * N + col]);
                    float2 o; o.x = v0 + rv.x; o.y = v1 + rv.y;
                    *reinterpret_cast<float2*>(&Cf[(size_t)row * N + col]) = o;
                } else {
                    *reinterpret_cast<uint32_t*>(&C16[(size_t)row * N + col]) = packh2(v0, v1);
                }
            }
        }
    }
}

// ---------------- causal flash attention (exp2-domain softmax) ----------------
#define QST 72
#define KST 72
#define VST 72
#define Q_SZ   (128 * QST)
#define K_OFF  Q_SZ
#define K_SZ   (64 * KST)
#define V_OFF  (K_OFF + 3 * K_SZ)
#define V_SZ   (64 * VST)
#define ATT_SMEM ((V_OFF + 3 * V_SZ) * 2)
#define S_SCALE (0.125f * 1.4426950408889634f)   // (1/8) * log2(e)

__global__ void __launch_bounds__(256, 2)
attn_kernel(const __half* __restrict__ qkv16, __half* __restrict__ out16) {
    extern __shared__ __half smh[];
    const uint32_t smem_u32 = (uint32_t)__cvta_generic_to_shared(smh);

    const int tid  = threadIdx.x;
    const int lane = tid & 31;
    const int warp = tid >> 5;
    const int lg = lane >> 2;
    const int lt = lane & 3;

    const int qb = gridDim.x - 1 - blockIdx.x;
    const int bh = blockIdx.y;
    const int b  = bh >> 4;
    const int h  = bh & 15;
    const int q0 = qb * 128;
    const size_t rowbase = (size_t)b * T_SEQ;

    const __half* qbase = qkv16 + rowbase * (3 * D_MODEL) + h * HDIM;

    {
        const int r = tid >> 1;
        const int c = (tid & 1) * 32;
        const uint32_t qdst = smem_u32 + (r * QST + c) * 2;
        const __half* qsrc = qbase + (size_t)(q0 + r) * (3 * D_MODEL) + c;
        cp16(qdst,      qsrc);
        cp16(qdst + 16, qsrc + 8);
        cp16(qdst + 32, qsrc + 16);
        cp16(qdst + 48, qsrc + 24);
    }

    const int kv_r = tid >> 2;
    const int kv_c = (tid & 3) * 16;

    auto prefetch = [&](int kb, int stg) {
        const uint32_t kdst = smem_u32 + (K_OFF + stg * K_SZ + kv_r * KST + kv_c) * 2;
        const uint32_t vdst = smem_u32 + (V_OFF + stg * V_SZ + kv_r * VST + kv_c) * 2;
        const __half* base = qbase + (size_t)(kb * 64 + kv_r) * (3 * D_MODEL);
        cp16(kdst,      base + D_MODEL + kv_c);
        cp16(kdst + 16, base + D_MODEL + kv_c + 8);
        cp16(vdst,      base + 2 * D_MODEL + kv_c);
        cp16(vdst + 16, base + 2 * D_MODEL + kv_c + 8);
    };

    float o[8][4];
    #pragma unroll
    for (int i = 0; i < 8; i++)
        #pragma unroll
        for (int j = 0; j < 4; j++) o[i][j] = 0.0f;
    float m0 = -INFINITY, m1 = -INFINITY;
    float l0 = 0.0f, l1 = 0.0f;

    const int nkb = 2 * qb + 2;
    prefetch(0, 0); cp_commit();
    prefetch(1, 1); cp_commit();

    const int qa_row = warp * 16 + (lane & 15);
    const int qa_co  = (lane >> 4) * 8;
    const int kb_row = (lane & 7) + ((lane >> 4) * 8);
    const int kb_co  = ((lane >> 3) & 1) * 8;
    const int vt_row = (lane & 7) + (((lane >> 3) & 1) * 8);
    const int vt_co  = (lane >> 4) * 8;

    for (int kb = 0; kb < nkb; kb++) {
        cp_wait1();
        __syncthreads();

        if (kb + 2 < nkb) prefetch(kb + 2, (kb + 2) % 3);
        cp_commit();

        const int stg = kb % 3;
        const uint32_t kbase = smem_u32 + (K_OFF + stg * K_SZ) * 2;
        const uint32_t vbase = smem_u32 + (V_OFF + stg * V_SZ) * 2;

        float s[8][4];
        #pragma unroll
        for (int i = 0; i < 8; i++)
            #pragma unroll
            for (int j = 0; j < 4; j++) s[i][j] = 0.0f;
        #pragma unroll
        for (int kt = 0; kt < 4; kt++) {
            const int kc = kt * 16;
            uint32_t a0, a1, a2, a3;
            ldsm4(a0, a1, a2, a3, smem_u32 + ((qa_row * QST) + kc + qa_co) * 2);
            #pragma unroll
            for (int ntp = 0; ntp < 4; ntp++) {
                uint32_t b0, b1, b2, b3;
                ldsm4(b0, b1, b2, b3, kbase + (((kb_row + ntp * 16) * KST) + kc + kb_co) * 2);
                mma_f16(s[2 * ntp],     a0, a1, a2, a3, b0, b1);
                mma_f16(s[2 * ntp + 1], a0, a1, a2, a3, b2, b3);
            }
        }
        #pragma unroll
        for (int nt = 0; nt < 8; nt++) {
            s[nt][0] *= S_SCALE; s[nt][1] *= S_SCALE;
            s[nt][2] *= S_SCALE; s[nt][3] *= S_SCALE;
        }

        const int t0 = kb * 64;
        if (t0 + 63 > q0 + warp * 16) {
            #pragma unroll
            for (int nt = 0; nt < 8; nt++) {
                #pragma unroll
                for (int j = 0; j < 4; j++) {
                    const int trow = q0 + warp * 16 + lg + (j >= 2 ? 8 : 0);
                    const int tcol = t0 + nt * 8 + 2 * lt + (j & 1);
                    if (tcol > trow) s[nt][j] = -INFINITY;
                }
            }
        }

        float mx0 = -INFINITY, mx1 = -INFINITY;
        #pragma unroll
        for (int nt = 0; nt < 8; nt++) {
            mx0 = fmaxf(mx0, fmaxf(s[nt][0], s[nt][1]));
            mx1 = fmaxf(mx1, fmaxf(s[nt][2], s[nt][3]));
        }
        mx0 = fmaxf(mx0, __shfl_xor_sync(0xffffffff, mx0, 1));
        mx0 = fmaxf(mx0, __shfl_xor_sync(0xffffffff, mx0, 2));
        mx1 = fmaxf(mx1, __shfl_xor_sync(0xffffffff, mx1, 1));
        mx1 = fmaxf(mx1, __shfl_xor_sync(0xffffffff, mx1, 2));
        const float mn0 = fmaxf(m0, mx0);
        const float mn1 = fmaxf(m1, mx1);

        float sum0 = 0.0f, sum1 = 0.0f;
        #pragma unroll
        for (int nt = 0; nt < 8; nt++) {
            s[nt][0] = exp2f(s[nt][0] - mn0);
            s[nt][1] = exp2f(s[nt][1] - mn0);
            s[nt][2] = exp2f(s[nt][2] - mn1);
            s[nt][3] = exp2f(s[nt][3] - mn1);
            sum0 += s[nt][0] + s[nt][1];
            sum1 += s[nt][2] + s[nt][3];
        }
        sum0 += __shfl_xor_sync(0xffffffff, sum0, 1);
        sum0 += __shfl_xor_sync(0xffffffff, sum0, 2);
        sum1 += __shfl_xor_sync(0xffffffff, sum1, 1);
        sum1 += __shfl_xor_sync(0xffffffff, sum1, 2);

        const float a0f = exp2f(m0 - mn0);
        const float a1f = exp2f(m1 - mn1);
        l0 = l0 * a0f + sum0;
        l1 = l1 * a1f + sum1;
        m0 = mn0; m1 = mn1;
        #pragma unroll
        for (int nt = 0; nt < 8; nt++) {
            o[nt][0] *= a0f; o[nt][1] *= a0f;
            o[nt][2] *= a1f; o[nt][3] *= a1f;
        }

        #pragma unroll
        for (int kt = 0; kt < 4; kt++) {
            const uint32_t a0 = packh2(s[2*kt][0],   s[2*kt][1]);
            const uint32_t a1 = packh2(s[2*kt][2],   s[2*kt][3]);
            const uint32_t a2 = packh2(s[2*kt+1][0], s[2*kt+1][1]);
            const uint32_t a3 = packh2(s[2*kt+1][2], s[2*kt+1][3]);
            #pragma unroll
            for (int ntp = 0; ntp < 4; ntp++) {
                uint32_t b0, b1, b2, b3;
                ldsm4t(b0, b1, b2, b3,
                       vbase + (((vt_row + kt * 16) * VST) + vt_co + ntp * 16) * 2);
                mma_f16(o[2 * ntp],     a0, a1, a2, a3, b0, b1);
                mma_f16(o[2 * ntp + 1], a0, a1, a2, a3, b2, b3);
            }
        }
    }

    const float inv0 = 1.0f / l0;
    const float inv1 = 1.0f / l1;
    #pragma unroll
    for (int nt = 0; nt < 8; nt++) {
        const int dcol = h * HDIM + nt * 8 + 2 * lt;
        const size_t r0 = rowbase + q0 + warp * 16 + lg;
        *reinterpret_cast<uint32_t*>(&out16[r0 * D_MODEL + dcol]) =
            packh2(o[nt][0] * inv0, o[nt][1] * inv0);
        *reinterpret_cast<uint32_t*>(&out16[(r0 + 8) * D_MODEL + dcol]) =
            packh2(o[nt][2] * inv1, o[nt][3] * inv1);
    }
}

// ---------------- launch ----------------
extern "C" void kernel_launch(void* const* d_in, const int* in_sizes, int n_in,
                              void* d_out, int out_size) {
    const float* x      = (const float*)d_in[0];
    const float* ln1_g  = (const float*)d_in[1];
    const float* ln1_b  = (const float*)d_in[2];
    const float* qkv_w  = (const float*)d_in[3];
    const float* qkv_b  = (const float*)d_in[4];
    const float* proj_w = (const float*)d_in[5];
    const float* proj_b = (const float*)d_in[6];
    const float* ln2_g  = (const float*)d_in[7];
    const float* ln2_b  = (const float*)d_in[8];
    const float* mlp_w1 = (const float*)d_in[9];
    const float* mlp_b1 = (const float*)d_in[10];
    const float* mlp_w2 = (const float*)d_in[11];
    const float* mlp_b2 = (const float*)d_in[12];
    float* out = (float*)d_out;

    __half *h16, *qkv16, *attn16, *h2_16, *ff16, *w16;
    float *x1;
    cudaGetSymbolAddress((void**)&h16,    g_h16);
    cudaGetSymbolAddress((void**)&qkv16,  g_qkv16);
    cudaGetSymbolAddress((void**)&attn16, g_attn16);
    cudaGetSymbolAddress((void**)&x1,     g_x1);
    cudaGetSymbolAddress((void**)&h2_16,  g_h2_16);
    cudaGetSymbolAddress((void**)&ff16,   g_ff16);
    cudaGetSymbolAddress((void**)&w16,    g_w16);

    cudaFuncSetAttribute(gemm16_kernel<0>, cudaFuncAttributeMaxDynamicSharedMemorySize, GEMM_SMEM16);
    cudaFuncSetAttribute(gemm16_kernel<1>, cudaFuncAttributeMaxDynamicSharedMemorySize, GEMM_SMEM16);
    cudaFuncSetAttribute(gemm16_kernel<2>, cudaFuncAttributeMaxDynamicSharedMemorySize, GEMM_SMEM16);
    cudaFuncSetAttribute(attn_kernel,      cudaFuncAttributeMaxDynamicSharedMemorySize, ATT_SMEM);

    // 0: ALL weights -> fp16, single launch
    cvt_all_kernel<<<W_TOT / 4 / 256, 256>>>(qkv_w, proj_w, mlp_w1, mlp_w2, w16);
    // 1: LN1 -> fp16
    ln_kernel<<<NROWS, 256>>>(x, ln1_g, ln1_b, h16);
    // 2: QKV GEMM -> fp16
    gemm16_kernel<0><<<dim3(3 * D_MODEL / 128, NROWS / 128), 256, GEMM_SMEM16>>>(
        h16, w16 + W_QKV, qkv_b, nullptr, nullptr, qkv16, NROWS, 3 * D_MODEL, D_MODEL);
    // 3: attention
    attn_kernel<<<dim3(T_SEQ / 128, BATCH * NHEADS), 256, ATT_SMEM>>>(qkv16, attn16);
    // 4: proj GEMM + residual (fp32)
    gemm16_kernel<2><<<dim3(D_MODEL / 128, NROWS / 128), 256, GEMM_SMEM16>>>(
        attn16, w16 + W_PROJ, proj_b, x, x1, nullptr, NROWS, D_MODEL, D_MODEL);
    // 5: LN2
    ln_kernel<<<NROWS, 256>>>(x1, ln2_g, ln2_b, h2_16);
    // 6: mlp1 + GELU
    gemm16_kernel<1><<<dim3(DFF / 128, NROWS / 128), 256, GEMM_SMEM16>>>(
        h2_16, w16 + W_MLP1, mlp_b1, nullptr, nullptr, ff16, NROWS, DFF, D_MODEL);
    // 7: mlp2 + residual
    gemm16_kernel<2><<<dim3(D_MODEL / 128, NROWS / 128), 256, GEMM_SMEM16>>>(
        ff16, w16 + W_MLP2, mlp_b2, x1, out, nullptr, NROWS, D_MODEL, DFF);
}

// round 17
// speedup vs baseline: 1.0350x; 1.0014x over previous
#include <cuda_runtime.h>
#include <cuda_fp16.h>
#include <stdint.h>
#include <math.h>

#define D_MODEL 1024
#define T_SEQ   2048
#define BATCH   2
#define NROWS   (BATCH * T_SEQ)
#define DFF     4096
#define NHEADS  16
#define HDIM    64

// ---------------- scratch ----------------
__device__ __align__(16) __half g_h16   [NROWS * D_MODEL];
__device__ __align__(16) __half g_qkv16 [NROWS * 3 * D_MODEL];
__device__ __align__(16) __half g_attn16[NROWS * D_MODEL];
__device__ __align__(16) float  g_x1    [NROWS * D_MODEL];
__device__ __align__(16) __half g_h2_16 [NROWS * D_MODEL];
__device__ __align__(16) __half g_ff16  [NROWS * DFF];
// fp16 weights, ORIGINAL [K][N] layout
#define SZ_QKV  (D_MODEL * 3 * D_MODEL)
#define SZ_PROJ (D_MODEL * D_MODEL)
#define SZ_MLP1 (D_MODEL * DFF)
#define SZ_MLP2 (DFF * D_MODEL)
#define W_QKV  0
#define W_PROJ (W_QKV + SZ_QKV)
#define W_MLP1 (W_PROJ + SZ_PROJ)
#define W_MLP2 (W_MLP1 + SZ_MLP1)
#define W_TOT  (W_MLP2 + SZ_MLP2)
__device__ __align__(16) __half g_w16[W_TOT];

// ---------------- helpers ----------------
__device__ __forceinline__ void mma_f16(float* d,
                                        uint32_t a0, uint32_t a1, uint32_t a2, uint32_t a3,
                                        uint32_t b0, uint32_t b1) {
    asm volatile(
        "mma.sync.aligned.m16n8k16.row.col.f32.f16.f16.f32 "
        "{%0,%1,%2,%3}, {%4,%5,%6,%7}, {%8,%9}, {%0,%1,%2,%3};\n"
        : "+f"(d[0]), "+f"(d[1]), "+f"(d[2]), "+f"(d[3])
        : "r"(a0), "r"(a1), "r"(a2), "r"(a3), "r"(b0), "r"(b1));
}

__device__ __forceinline__ void ldsm4(uint32_t& r0, uint32_t& r1, uint32_t& r2, uint32_t& r3,
                                      uint32_t addr) {
    asm volatile("ldmatrix.sync.aligned.m8n8.x4.shared.b16 {%0,%1,%2,%3}, [%4];"
                 : "=r"(r0), "=r"(r1), "=r"(r2), "=r"(r3) : "r"(addr));
}
__device__ __forceinline__ void ldsm4t(uint32_t& r0, uint32_t& r1, uint32_t& r2, uint32_t& r3,
                                       uint32_t addr) {
    asm volatile("ldmatrix.sync.aligned.m8n8.x4.trans.shared.b16 {%0,%1,%2,%3}, [%4];"
                 : "=r"(r0), "=r"(r1), "=r"(r2), "=r"(r3) : "r"(addr));
}

__device__ __forceinline__ uint32_t packh2(float lo, float hi) {
    __half2 h = __floats2half2_rn(lo, hi);
    return *reinterpret_cast<uint32_t*>(&h);
}

__device__ __forceinline__ void cp16(uint32_t s, const void* g) {
    asm volatile("cp.async.cg.shared.global [%0], [%1], 16;\n" :: "r"(s), "l"(g));
}
__device__ __forceinline__ void cp_commit() { asm volatile("cp.async.commit_group;\n"); }
__device__ __forceinline__ void cp_wait1()  { asm volatile("cp.async.wait_group 1;\n"); }

// ---------------- merged weight fp16 convert ----------------
__global__ void __launch_bounds__(256)
cvt_all_kernel(const float* __restrict__ s0, const float* __restrict__ s1,
               const float* __restrict__ s2, const float* __restrict__ s3,
               __half* __restrict__ dst) {
    const int i = blockIdx.x * blockDim.x + threadIdx.x;
    const int e = i * 4;
    const float* src;
    int off;
    if (e < W_PROJ)      { src = s0; off = e - W_QKV;  }
    else if (e < W_MLP1) { src = s1; off = e - W_PROJ; }
    else if (e < W_MLP2) { src = s2; off = e - W_MLP1; }
    else                 { src = s3; off = e - W_MLP2; }
    const float4 v = *reinterpret_cast<const float4*>(src + off);
    uint2 o;
    o.x = packh2(v.x, v.y);
    o.y = packh2(v.z, v.w);
    reinterpret_cast<uint2*>(dst)[i] = o;
}

// ---------------- layernorm (fp16 output) ----------------
__global__ void ln_kernel(const float* __restrict__ x,
                          const float* __restrict__ g,
                          const float* __restrict__ b,
                          __half* __restrict__ out) {
    const int row = blockIdx.x;
    const int tid = threadIdx.x;
    const float4 v = reinterpret_cast<const float4*>(x + (size_t)row * D_MODEL)[tid];
    float s  = v.x + v.y + v.z + v.w;
    float sq = v.x*v.x + v.y*v.y + v.z*v.z + v.w*v.w;

    __shared__ float rs[256];
    __shared__ float rq[256];
    rs[tid] = s; rq[tid] = sq;
    __syncthreads();
    #pragma unroll
    for (int st = 128; st > 0; st >>= 1) {
        if (tid < st) { rs[tid] += rs[tid + st]; rq[tid] += rq[tid + st]; }
        __syncthreads();
    }
    const float mean = rs[0] * (1.0f / D_MODEL);
    const float var  = rq[0] * (1.0f / D_MODEL) - mean * mean;
    const float rstd = rsqrtf(var + 1e-5f);

    const float4 gv = reinterpret_cast<const float4*>(g)[tid];
    const float4 bv = reinterpret_cast<const float4*>(b)[tid];
    uint2 o;
    o.x = packh2((v.x - mean) * rstd * gv.x + bv.x, (v.y - mean) * rstd * gv.y + bv.y);
    o.y = packh2((v.z - mean) * rstd * gv.z + bv.z, (v.w - mean) * rstd * gv.w + bv.w);
    *reinterpret_cast<uint2*>(out + (size_t)row * D_MODEL + tid * 4) = o;
}

// ---------------- fp16 GEMM (proven): 128x128, B [K][N] trans-LDSM, 5 stages, pair ----
#define GBK   32
#define GST   40
#define BSN   136
#define A_H   (128 * GST)
#define B_H   (32 * BSN)
#define ST_H  (A_H + B_H)
#define GSTAGES 5
#define GEMM_SMEM16 (GSTAGES * ST_H * 2)   // 94720 bytes

template<int EPI>
__global__ void __launch_bounds__(256, 2)
gemm16_kernel(const __half* __restrict__ A, const __half* __restrict__ B,
              const float* __restrict__ bias, const float* __restrict__ res,
              float* __restrict__ Cf, __half* __restrict__ C16,
              int M, int N, int K) {
    extern __shared__ __half smh[];
    const uint32_t smem_u32 = (uint32_t)__cvta_generic_to_shared(smh);

    const int tid    = threadIdx.x;
    const int lane   = tid & 31;
    const int warp   = tid >> 5;
    const int warp_m = warp >> 1;
    const int warp_n = warp & 1;
    const int bm = blockIdx.y * 128;
    const int bn = blockIdx.x * 128;
    const int lg = lane >> 2;
    const int lt = lane & 3;

    float c[2][8][4];
    #pragma unroll
    for (int i = 0; i < 2; i++)
        #pragma unroll
        for (int j = 0; j < 8; j++)
            #pragma unroll
            for (int k = 0; k < 4; k++) c[i][j][k] = 0.0f;

    const int a_r = tid >> 1;
    const int a_c = (tid & 1) * 16;
    const int b_r = tid >> 3;
    const int b_c = (tid & 7) * 16;
    const int KT = K / GBK;

    auto load_stage = [&](int kt, int stg) {
        const uint32_t ab = smem_u32 + (stg * ST_H + a_r * GST + a_c) * 2;
        const __half* as = &A[(size_t)(bm + a_r) * K + kt * GBK + a_c];
        cp16(ab,      as);
        cp16(ab + 16, as + 8);
        const uint32_t bb = smem_u32 + (stg * ST_H + A_H + b_r * BSN + b_c) * 2;
        const __half* bs = &B[(size_t)(kt * GBK + b_r) * N + bn + b_c];
        cp16(bb,      bs);
        cp16(bb + 16, bs + 8);
        cp_commit();
    };

    load_stage(0, 0);
    load_stage(1, 1);
    load_stage(2, 2);

    const int a_row  = warp_m * 32 + (lane & 15);
    const int a_co   = (lane >> 4) * 8;
    const int bt_row = (lane & 7) + (((lane >> 3) & 1) * 8);
    const int bt_co  = (lane >> 4) * 8;

    for (int kt = 0; kt < KT; kt += 2) {
        cp_wait1();
        __syncthreads();

        if (kt + 3 < KT) load_stage(kt + 3, (kt + 3) % GSTAGES); else cp_commit();
        if (kt + 4 < KT) load_stage(kt + 4, (kt + 4) % GSTAGES); else cp_commit();

        #pragma unroll
        for (int hf = 0; hf < 2; hf++) {
            const uint32_t abase = smem_u32 + (((kt + hf) % GSTAGES) * ST_H) * 2;
            const uint32_t bbase = abase + A_H * 2;

            #pragma unroll
            for (int ks = 0; ks < 2; ks++) {
                const int kc = ks * 16;
                uint32_t af[2][4];
                #pragma unroll
                for (int mi = 0; mi < 2; mi++)
                    ldsm4(af[mi][0], af[mi][1], af[mi][2], af[mi][3],
                          abase + (((a_row + mi * 16) * GST) + kc + a_co) * 2);
                #pragma unroll
                for (int ntp = 0; ntp < 4; ntp++) {
                    uint32_t b0, b1, b2, b3;
                    ldsm4t(b0, b1, b2, b3,
                           bbase + (((bt_row + kc) * BSN) + bt_co + warp_n * 64 + ntp * 16) * 2);
                    #pragma unroll
                    for (int mi = 0; mi < 2; mi++) {
                        mma_f16(c[mi][2 * ntp],     af[mi][0], af[mi][1], af[mi][2], af[mi][3],
                                b0, b1);
                        mma_f16(c[mi][2 * ntp + 1], af[mi][0], af[mi][1], af[mi][2], af[mi][3],
                                b2, b3);
                    }
                }
            }
        }
    }

    const float inv_sqrt2 = 0.70710678118654752f;
    #pragma unroll
    for (int mi = 0; mi < 2; mi++) {
        #pragma unroll
        for (int nt = 0; nt < 8; nt++) {
            const int col = bn + warp_n * 64 + nt * 8 + 2 * lt;
            const float2 bb = *reinterpret_cast<const float2*>(&bias[col]);
            #pragma unroll
            for (int half = 0; half < 2; half++) {
                const int row = bm + warp_m * 32 + mi * 16 + lg + half * 8;
                float v0 = c[mi][nt][half * 2 + 0] + bb.x;
                float v1 = c[mi][nt][half * 2 + 1] + bb.y;
                if (EPI == 1) {
                    v0 = 0.5f * v0 * (1.0f + erff(v0 * inv_sqrt2));
                    v1 = 0.5f * v1 * (1.0f + erff(v1 * inv_sqrt2));
                }
                if (EPI == 2) {
                    const float2 rv = *reinterpret_cast<const float2*>(&res[(size_t)row * N + col]);
                    float2 o; o.x = v0 + rv.x; o.y = v1 + rv.y;
                    *reinterpret_cast<float2*>(&Cf[(size_t)row * N + col]) = o;
                } else {
                    *reinterpret_cast<uint32_t*>(&C16[(size_t)row * N + col]) = packh2(v0, v1);
                }
            }
        }
    }
}

// ---------------- causal flash attention: 5-stage, pair-processed, exp2 softmax ----------------
#define QST 72
#define KST 72
#define VST 72
#define Q_SZ   (128 * QST)
#define KV_STG 5
#define K_OFF  Q_SZ
#define K_SZ   (64 * KST)
#define V_OFF  (K_OFF + KV_STG * K_SZ)
#define V_SZ   (64 * VST)
#define ATT_SMEM ((V_OFF + KV_STG * V_SZ) * 2)   // (9216 + 5*4608 + 5*4608)*2 = 110592 B
#define S_SCALE (0.125f * 1.4426950408889634f)

__global__ void __launch_bounds__(256, 2)
attn_kernel(const __half* __restrict__ qkv16, __half* __restrict__ out16) {
    extern __shared__ __half smh[];
    const uint32_t smem_u32 = (uint32_t)__cvta_generic_to_shared(smh);

    const int tid  = threadIdx.x;
    const int lane = tid & 31;
    const int warp = tid >> 5;
    const int lg = lane >> 2;
    const int lt = lane & 3;

    const int qb = gridDim.x - 1 - blockIdx.x;
    const int bh = blockIdx.y;
    const int b  = bh >> 4;
    const int h  = bh & 15;
    const int q0 = qb * 128;
    const size_t rowbase = (size_t)b * T_SEQ;

    const __half* qbase = qkv16 + rowbase * (3 * D_MODEL) + h * HDIM;

    {
        const int r = tid >> 1;
        const int c = (tid & 1) * 32;
        const uint32_t qdst = smem_u32 + (r * QST + c) * 2;
        const __half* qsrc = qbase + (size_t)(q0 + r) * (3 * D_MODEL) + c;
        cp16(qdst,      qsrc);
        cp16(qdst + 16, qsrc + 8);
        cp16(qdst + 32, qsrc + 16);
        cp16(qdst + 48, qsrc + 24);
    }

    const int kv_r = tid >> 2;
    const int kv_c = (tid & 3) * 16;

    auto prefetch = [&](int kb, int stg) {
        const uint32_t kdst = smem_u32 + (K_OFF + stg * K_SZ + kv_r * KST + kv_c) * 2;
        const uint32_t vdst = smem_u32 + (V_OFF + stg * V_SZ + kv_r * VST + kv_c) * 2;
        const __half* base = qbase + (size_t)(kb * 64 + kv_r) * (3 * D_MODEL);
        cp16(kdst,      base + D_MODEL + kv_c);
        cp16(kdst + 16, base + D_MODEL + kv_c + 8);
        cp16(vdst,      base + 2 * D_MODEL + kv_c);
        cp16(vdst + 16, base + 2 * D_MODEL + kv_c + 8);
        cp_commit();
    };

    float o[8][4];
    #pragma unroll
    for (int i = 0; i < 8; i++)
        #pragma unroll
        for (int j = 0; j < 4; j++) o[i][j] = 0.0f;
    float m0 = -INFINITY, m1 = -INFINITY;
    float l0 = 0.0f, l1 = 0.0f;

    const int nkb = 2 * qb + 2;   // always even
    prefetch(0, 0);               // C0 (includes Q)
    prefetch(1, 1);               // C1
    prefetch(2, 2 % KV_STG);      // C2 (kb=2 may exceed nkb only when qb=0: nkb=2, then 2<nkb false)
    // note: guard the third prefetch
    // (we re-issue an empty commit if out of range to keep group accounting uniform)

    const int qa_row = warp * 16 + (lane & 15);
    const int qa_co  = (lane >> 4) * 8;
    const int kb_row = (lane & 7) + ((lane >> 4) * 8);
    const int kb_co  = ((lane >> 3) & 1) * 8;
    const int vt_row = (lane & 7) + (((lane >> 3) & 1) * 8);
    const int vt_co  = (lane >> 4) * 8;

    for (int kb = 0; kb < nkb; kb += 2) {
        cp_wait1();
        __syncthreads();

        if (kb + 3 < nkb) prefetch(kb + 3, (kb + 3) % KV_STG); else cp_commit();
        if (kb + 4 < nkb) prefetch(kb + 4, (kb + 4) % KV_STG); else cp_commit();

        #pragma unroll
        for (int hf = 0; hf < 2; hf++) {
            const int kbi = kb + hf;
            const int stg = kbi % KV_STG;
            const uint32_t kbase = smem_u32 + (K_OFF + stg * K_SZ) * 2;
            const uint32_t vbase = smem_u32 + (V_OFF + stg * V_SZ) * 2;

            float s[8][4];
            #pragma unroll
            for (int i = 0; i < 8; i++)
                #pragma unroll
                for (int j = 0; j < 4; j++) s[i][j] = 0.0f;
            #pragma unroll
            for (int kt = 0; kt < 4; kt++) {
                const int kc = kt * 16;
                uint32_t a0, a1, a2, a3;
                ldsm4(a0, a1, a2, a3, smem_u32 + ((qa_row * QST) + kc + qa_co) * 2);
                #pragma unroll
                for (int ntp = 0; ntp < 4; ntp++) {
                    uint32_t b0, b1, b2, b3;
                    ldsm4(b0, b1, b2, b3, kbase + (((kb_row + ntp * 16) * KST) + kc + kb_co) * 2);
                    mma_f16(s[2 * ntp],     a0, a1, a2, a3, b0, b1);
                    mma_f16(s[2 * ntp + 1], a0, a1, a2, a3, b2, b3);
                }
            }
            #pragma unroll
            for (int nt = 0; nt < 8; nt++) {
                s[nt][0] *= S_SCALE; s[nt][1] *= S_SCALE;
                s[nt][2] *= S_SCALE; s[nt][3] *= S_SCALE;
            }

            const int t0 = kbi * 64;
            if (t0 + 63 > q0 + warp * 16) {
                #pragma unroll
                for (int nt = 0; nt < 8; nt++) {
                    #pragma unroll
                    for (int j = 0; j < 4; j++) {
                        const int trow = q0 + warp * 16 + lg + (j >= 2 ? 8 : 0);
                        const int tcol = t0 + nt * 8 + 2 * lt + (j & 1);
                        if (tcol > trow) s[nt][j] = -INFINITY;
                    }
                }
            }

            float mx0 = -INFINITY, mx1 = -INFINITY;
            #pragma unroll
            for (int nt = 0; nt < 8; nt++) {
                mx0 = fmaxf(mx0, fmaxf(s[nt][0], s[nt][1]));
                mx1 = fmaxf(mx1, fmaxf(s[nt][2], s[nt][3]));
            }
            mx0 = fmaxf(mx0, __shfl_xor_sync(0xffffffff, mx0, 1));
            mx0 = fmaxf(mx0, __shfl_xor_sync(0xffffffff, mx0, 2));
            mx1 = fmaxf(mx1, __shfl_xor_sync(0xffffffff, mx1, 1));
            mx1 = fmaxf(mx1, __shfl_xor_sync(0xffffffff, mx1, 2));
            const float mn0 = fmaxf(m0, mx0);
            const float mn1 = fmaxf(m1, mx1);

            float sum0 = 0.0f, sum1 = 0.0f;
            #pragma unroll
            for (int nt = 0; nt < 8; nt++) {
                s[nt][0] = exp2f(s[nt][0] - mn0);
                s[nt][1] = exp2f(s[nt][1] - mn0);
                s[nt][2] = exp2f(s[nt][2] - mn1);
                s[nt][3] = exp2f(s[nt][3] - mn1);
                sum0 += s[nt][0] + s[nt][1];
                sum1 += s[nt][2] + s[nt][3];
            }
            sum0 += __shfl_xor_sync(0xffffffff, sum0, 1);
            sum0 += __shfl_xor_sync(0xffffffff, sum0, 2);
            sum1 += __shfl_xor_sync(0xffffffff, sum1, 1);
            sum1 += __shfl_xor_sync(0xffffffff, sum1, 2);

            const float a0f = exp2f(m0 - mn0);
            const float a1f = exp2f(m1 - mn1);
            l0 = l0 * a0f + sum0;
            l1 = l1 * a1f + sum1;
            m0 = mn0; m1 = mn1;
            #pragma unroll
            for (int nt = 0; nt < 8; nt++) {
                o[nt][0] *= a0f; o[nt][1] *= a0f;
                o[nt][2] *= a1f; o[nt][3] *= a1f;
            }

            #pragma unroll
            for (int kt = 0; kt < 4; kt++) {
                const uint32_t a0 = packh2(s[2*kt][0],   s[2*kt][1]);
                const uint32_t a1 = packh2(s[2*kt][2],   s[2*kt][3]);
                const uint32_t a2 = packh2(s[2*kt+1][0], s[2*kt+1][1]);
                const uint32_t a3 = packh2(s[2*kt+1][2], s[2*kt+1][3]);
                #pragma unroll
                for (int ntp = 0; ntp < 4; ntp++) {
                    uint32_t b0, b1, b2, b3;
                    ldsm4t(b0, b1, b2, b3,
                           vbase + (((vt_row + kt * 16) * VST) + vt_co + ntp * 16) * 2);
                    mma_f16(o[2 * ntp],     a0, a1, a2, a3, b0, b1);
                    mma_f16(o[2 * ntp + 1], a0, a1, a2, a3, b2, b3);
                }
            }
        }
    }

    const float inv0 = 1.0f / l0;
    const float inv1 = 1.0f / l1;
    #pragma unroll
    for (int nt = 0; nt < 8; nt++) {
        const int dcol = h * HDIM + nt * 8 + 2 * lt;
        const size_t r0 = rowbase + q0 + warp * 16 + lg;
        *reinterpret_cast<uint32_t*>(&out16[r0 * D_MODEL + dcol]) =
            packh2(o[nt][0] * inv0, o[nt][1] * inv0);
        *reinterpret_cast<uint32_t*>(&out16[(r0 + 8) * D_MODEL + dcol]) =
            packh2(o[nt][2] * inv1, o[nt][3] * inv1);
    }
}

// ---------------- launch ----------------
extern "C" void kernel_launch(void* const* d_in, const int* in_sizes, int n_in,
                              void* d_out, int out_size) {
    const float* x      = (const float*)d_in[0];
    const float* ln1_g  = (const float*)d_in[1];
    const float* ln1_b  = (const float*)d_in[2];
    const float* qkv_w  = (const float*)d_in[3];
    const float* qkv_b  = (const float*)d_in[4];
    const float* proj_w = (const float*)d_in[5];
    const float* proj_b = (const float*)d_in[6];
    const float* ln2_g  = (const float*)d_in[7];
    const float* ln2_b  = (const float*)d_in[8];
    const float* mlp_w1 = (const float*)d_in[9];
    const float* mlp_b1 = (const float*)d_in[10];
    const float* mlp_w2 = (const float*)d_in[11];
    const float* mlp_b2 = (const float*)d_in[12];
    float* out = (float*)d_out;

    __half *h16, *qkv16, *attn16, *h2_16, *ff16, *w16;
    float *x1;
    cudaGetSymbolAddress((void**)&h16,    g_h16);
    cudaGetSymbolAddress((void**)&qkv16,  g_qkv16);
    cudaGetSymbolAddress((void**)&attn16, g_attn16);
    cudaGetSymbolAddress((void**)&x1,     g_x1);
    cudaGetSymbolAddress((void**)&h2_16,  g_h2_16);
    cudaGetSymbolAddress((void**)&ff16,   g_ff16);
    cudaGetSymbolAddress((void**)&w16,    g_w16);

    cudaFuncSetAttribute(gemm16_kernel<0>, cudaFuncAttributeMaxDynamicSharedMemorySize, GEMM_SMEM16);
    cudaFuncSetAttribute(gemm16_kernel<1>, cudaFuncAttributeMaxDynamicSharedMemorySize, GEMM_SMEM16);
    cudaFuncSetAttribute(gemm16_kernel<2>, cudaFuncAttributeMaxDynamicSharedMemorySize, GEMM_SMEM16);
    cudaFuncSetAttribute(attn_kernel,      cudaFuncAttributeMaxDynamicSharedMemorySize, ATT_SMEM);

    // 0: ALL weights -> fp16, single launch
    cvt_all_kernel<<<W_TOT / 4 / 256, 256>>>(qkv_w, proj_w, mlp_w1, mlp_w2, w16);
    // 1: LN1 -> fp16
    ln_kernel<<<NROWS, 256>>>(x, ln1_g, ln1_b, h16);
    // 2: QKV GEMM -> fp16
    gemm16_kernel<0><<<dim3(3 * D_MODEL / 128, NROWS / 128), 256, GEMM_SMEM16>>>(
        h16, w16 + W_QKV, qkv_b, nullptr, nullptr, qkv16, NROWS, 3 * D_MODEL, D_MODEL);
    // 3: attention
    attn_kernel<<<dim3(T_SEQ / 128, BATCH * NHEADS), 256, ATT_SMEM>>>(qkv16, attn16);
    // 4: proj GEMM + residual (fp32)
    gemm16_kernel<2><<<dim3(D_MODEL / 128, NROWS / 128), 256, GEMM_SMEM16>>>(
        attn16, w16 + W_PROJ, proj_b, x, x1, nullptr, NROWS, D_MODEL, D_MODEL);
    // 5: LN2
    ln_kernel<<<NROWS, 256>>>(x1, ln2_g, ln2_b, h2_16);
    // 6: mlp1 + GELU
    gemm16_kernel<1><<<dim3(DFF / 128, NROWS / 128), 256, GEMM_SMEM16>>>(
        h2_16, w16 + W_MLP1, mlp_b1, nullptr, nullptr, ff16, NROWS, DFF, D_MODEL);
    // 7: mlp2 + residual
    gemm16_kernel<2><<<dim3(D_MODEL / 128, NROWS / 128), 256, GEMM_SMEM16>>>(
        ff16, w16 + W_MLP2, mlp_b2, x1, out, nullptr, NROWS, D_MODEL, DFF);
}